// round 3
// baseline (speedup 1.0000x reference)
#include <cuda_runtime.h>
#include <cstdint>
#include <math.h>

#define NB   8192
#define FST  257

__device__ unsigned g_m1[NB * 8];
__device__ unsigned g_m2[NB * 8];
__device__ float    g_f[NB * 64];

typedef unsigned long long ull;
static __device__ __forceinline__ ull dup2(float x) {
    unsigned xi = __float_as_uint(x); ull r;
    asm("mov.b64 %0, {%1, %1};" : "=l"(r) : "r"(xi)); return r;
}
static __device__ __forceinline__ ull fma2(ull a, ull b, ull c) {
    ull d; asm("fma.rn.f32x2 %0, %1, %2, %3;" : "=l"(d) : "l"(a), "l"(b), "l"(c)); return d;
}
static __device__ __forceinline__ float2 unp2(ull v) {
    unsigned lo, hi; asm("mov.b64 {%0, %1}, %2;" : "=r"(lo), "=r"(hi) : "l"(v));
    return make_float2(__uint_as_float(lo), __uint_as_float(hi));
}

// ================= forward: 3-layer MLP + masks =================
__global__ void __launch_bounds__(256, 1)
fwd_kernel(const float* __restrict__ x,
           const float* __restrict__ W1, const float* __restrict__ b1,
           const float* __restrict__ W2, const float* __restrict__ b2,
           const float* __restrict__ W3, const float* __restrict__ b3)
{
    extern __shared__ float sm[];
    float* bufA = sm;
    float* bufB = bufA + 64 * FST;
    float* wt   = bufB + 64 * FST;
    const int tid = threadIdx.x;
    const int s0  = blockIdx.x * 64;
    const int tx = tid & 15, ty = tid >> 4;

    for (int e = tid; e < 64 * 64; e += 256) {
        int r = e >> 6, c = e & 63;
        float4 v = reinterpret_cast<const float4*>(x)[(size_t)(s0 + r) * 64 + c];
        float* d = &bufA[r * FST + c * 4];
        d[0] = v.x; d[1] = v.y; d[2] = v.z; d[3] = v.w;
    }
    __syncthreads();

    const float* Ws[3] = {W1, W2, W3};
    const float* bs[3] = {b1, b2, b3};
    float* ib = bufA;
    float* ob = bufB;

    for (int L = 0; L < 3; L++) {
        const int HO = (L == 2) ? 64 : 256;
        for (int oc = 0; oc < HO / 64; oc++) {
            __syncthreads();
            for (int e = tid; e < 64 * 64; e += 256) {
                int r = e >> 6, c = e & 63;
                float4 v = reinterpret_cast<const float4*>(Ws[L])[(size_t)(oc * 64 + r) * 64 + c];
                float* d = &wt[r * FST + c * 4];
                d[0] = v.x; d[1] = v.y; d[2] = v.z; d[3] = v.w;
            }
            __syncthreads();

            float acc[4][4];
            #pragma unroll
            for (int u = 0; u < 4; u++) {
                float bv = bs[L][oc * 64 + tx + 16 * u];
                #pragma unroll
                for (int i = 0; i < 4; i++) acc[i][u] = bv;
            }
            #pragma unroll 4
            for (int k = 0; k < 256; k++) {
                float a[4], bv[4];
                #pragma unroll
                for (int i = 0; i < 4; i++) a[i] = ib[(ty * 4 + i) * FST + k];
                #pragma unroll
                for (int u = 0; u < 4; u++) bv[u] = wt[(tx + 16 * u) * FST + k];
                #pragma unroll
                for (int i = 0; i < 4; i++)
                    #pragma unroll
                    for (int u = 0; u < 4; u++)
                        acc[i][u] = fmaf(a[i], bv[u], acc[i][u]);
            }
            if (L < 2) {
                #pragma unroll
                for (int i = 0; i < 4; i++)
                    #pragma unroll
                    for (int u = 0; u < 4; u++)
                        ob[(ty * 4 + i) * FST + oc * 64 + tx + 16 * u] = fmaxf(acc[i][u], 0.f);
            } else {
                #pragma unroll
                for (int i = 0; i < 4; i++)
                    #pragma unroll
                    for (int u = 0; u < 4; u++)
                        g_f[(size_t)(s0 + ty * 4 + i) * 64 + tx + 16 * u] = acc[i][u];
            }
        }
        if (L < 2) {
            __syncthreads();
            unsigned* mg = L ? g_m2 : g_m1;
            for (int e = tid; e < 64 * 8; e += 256) {
                int s = e >> 3, w = e & 7;
                unsigned bits = 0;
                for (int bb = 0; bb < 32; bb++)
                    if (ob[s * FST + w * 32 + bb] > 0.f) bits |= 1u << bb;
                mg[(size_t)(s0 + s) * 8 + w] = bits;
            }
            float* t = ib; ib = ob; ob = t;
            __syncthreads();
        }
    }
}

// ================= Jacobian Frobenius norm + epilogue =================
// smem (floats): W1s[32*256] | As[64*65] | Wgs[64*34] | Bts[64*33] | idx1[256] idx2[256] cnts[2] red[8] pcnt[16]
#define SM_W1S 0
#define SM_AS  8192
#define SM_WGS 12352
#define SM_BTS 14528
#define SM_IDX1 16640
#define SM_IDX2 16896
#define SM_CNT 17152
#define SM_RED 17154
#define SM_PC  17162
#define SM_JAC_BYTES ((17162 + 16) * 4)

__global__ void __launch_bounds__(256, 2)
jac_kernel(const float* __restrict__ W1, const float* __restrict__ W2,
           const float* __restrict__ W3, const float* __restrict__ kp,
           float* __restrict__ out)
{
    extern __shared__ float sm[];
    float* W1s = sm + SM_W1S;
    float* As  = sm + SM_AS;
    float* Wgs = sm + SM_WGS;
    float* Bts = sm + SM_BTS;
    int* idx1  = (int*)(sm + SM_IDX1);
    int* idx2  = (int*)(sm + SM_IDX2);
    int* cnts  = (int*)(sm + SM_CNT);
    float* red = sm + SM_RED;
    int* pcnt  = (int*)(sm + SM_PC);

    const int b = blockIdx.x;
    const int tid = threadIdx.x;
    const int tx = tid & 15, ty = tid >> 4;

    idx1[tid] = 0; idx2[tid] = 0;
    if (tid < 16) {
        int which = tid >> 3, w = tid & 7;
        unsigned word = (which ? g_m2 : g_m1)[(size_t)b * 8 + w];
        pcnt[tid] = __popc(word);
    }
    __syncthreads();
    if (tid < 16) {
        int which = tid >> 3, w = tid & 7;
        unsigned word = (which ? g_m2 : g_m1)[(size_t)b * 8 + w];
        int base = 0;
        for (int t = which * 8; t < which * 8 + w; t++) base += pcnt[t];
        int* idx = which ? idx2 : idx1;
        while (word) {
            int bp = __ffs(word) - 1; word &= word - 1;
            idx[base++] = w * 32 + bp;
        }
        if (w == 7) cnts[which] = base;
    }
    __syncthreads();
    const int cnt1 = cnts[0], cnt2 = cnts[1];
    const int n1 = (cnt1 + 31) & ~31;
    const int n2 = (cnt2 + 63) & ~63;

    const int jj = tx * 2;           // step2: local j pair
    const int ob = ty * 4;           // step2: 4 o's
    ull C[4][8];
    #pragma unroll
    for (int i = 0; i < 4; i++)
        #pragma unroll
        for (int u = 0; u < 8; u++) C[i][u] = 0ull;

    for (int j0 = 0; j0 < n1; j0 += 32) {
        __syncthreads();
        // stage 32 gathered W1 rows (coalesced float4)
        for (int e = tid; e < 32 * 64; e += 256) {
            int jt = e >> 6, c = e & 63;
            int row = idx1[j0 + jt];
            float4 v = reinterpret_cast<const float4*>(W1)[(size_t)row * 64 + c];
            float* d = &W1s[jt * 256 + c * 4];
            d[0] = v.x; d[1] = v.y; d[2] = v.z; d[3] = v.w;
        }
        ull bacc[4] = {0ull, 0ull, 0ull, 0ull};
        for (int i0 = 0; i0 < n2; i0 += 64) {
            __syncthreads();
            // stage A[ii][o] = W3[o, idx2[i0+ii]] (0 for pad i)
            for (int e = tid; e < 64 * 64; e += 256) {
                int ii = e & 63, o = e >> 6;
                As[ii * 65 + o] = (i0 + ii < cnt2) ? W3[(size_t)o * 256 + idx2[i0 + ii]] : 0.f;
            }
            // stage Wg[ii][jt] = W2[idx2[i0+ii], idx1[j0+jt]]
            for (int e = tid; e < 64 * 32; e += 256) {
                int jt = e & 31, ii = e >> 5;
                Wgs[ii * 34 + jt] = W2[(size_t)idx2[i0 + ii] * 256 + idx1[j0 + jt]];
            }
            __syncthreads();
            #pragma unroll 4
            for (int ii = 0; ii < 64; ii++) {
                ull w2 = *(const ull*)&Wgs[ii * 34 + jj];
                #pragma unroll
                for (int i = 0; i < 4; i++)
                    bacc[i] = fma2(dup2(As[ii * 65 + ob + i]), w2, bacc[i]);
            }
        }
        __syncthreads();
        #pragma unroll
        for (int i = 0; i < 4; i++) {
            float2 p = unp2(bacc[i]);
            Bts[(ob + i) * 33 + jj]     = (j0 + jj     < cnt1) ? p.x : 0.f;
            Bts[(ob + i) * 33 + jj + 1] = (j0 + jj + 1 < cnt1) ? p.y : 0.f;
        }
        __syncthreads();
        // step3: C[o, d] += Bt[o, jt] * W1s[jt, d]
        #pragma unroll 2
        for (int jt = 0; jt < 32; jt++) {
            float bt[4];
            #pragma unroll
            for (int i = 0; i < 4; i++) bt[i] = Bts[(ty + 16 * i) * 33 + jt];
            #pragma unroll
            for (int u = 0; u < 8; u++) {
                ull w = *(const ull*)&W1s[jt * 256 + tx * 2 + 32 * u];
                #pragma unroll
                for (int i = 0; i < 4; i++)
                    C[i][u] = fma2(dup2(bt[i]), w, C[i][u]);
            }
        }
    }

    float q = 0.f;
    #pragma unroll
    for (int i = 0; i < 4; i++)
        #pragma unroll
        for (int u = 0; u < 8; u++) {
            float2 c = unp2(C[i][u]);
            q += c.x * c.x + c.y * c.y;
        }
    #pragma unroll
    for (int s = 16; s; s >>= 1) q += __shfl_xor_sync(0xFFFFFFFFu, q, s);
    if ((tid & 31) == 0) red[tid >> 5] = q;
    __syncthreads();
    if (tid == 0) {
        float t = 0.f;
        for (int i = 0; i < 8; i++) t += red[i];
        red[0] = t;
    }
    __syncthreads();
    const float qq = red[0];
    if (tid < 64) {
        float fv = g_f[(size_t)b * 64 + tid];
        float kk = kp[0];
        float sp = (kk > 20.f) ? kk : log1pf(expf(kk));
        out[(size_t)b * 64 + tid] = tanhf(sp * fv / (sqrtf(qq) + 1e-4f));
    }
}

extern "C" void kernel_launch(void* const* d_in, const int* in_sizes, int n_in,
                              void* d_out, int out_size) {
    const float* x  = (const float*)d_in[0];
    const float* W1 = (const float*)d_in[1];
    const float* b1 = (const float*)d_in[2];
    const float* W2 = (const float*)d_in[3];
    const float* b2 = (const float*)d_in[4];
    const float* W3 = (const float*)d_in[5];
    const float* b3 = (const float*)d_in[6];
    const float* k  = (const float*)d_in[7];
    float* out = (float*)d_out;

    const size_t sm_fwd = 3 * 64 * FST * sizeof(float);
    cudaFuncSetAttribute(fwd_kernel, cudaFuncAttributeMaxDynamicSharedMemorySize, (int)sm_fwd);
    cudaFuncSetAttribute(jac_kernel, cudaFuncAttributeMaxDynamicSharedMemorySize, SM_JAC_BYTES);

    fwd_kernel<<<128, 256, sm_fwd>>>(x, W1, b1, W2, b2, W3, b3);
    jac_kernel<<<NB, 256, SM_JAC_BYTES>>>(W1, W2, W3, k, out);
}

// round 4
// speedup vs baseline: 1.6478x; 1.6478x over previous
#include <cuda_runtime.h>
#include <cstdint>
#include <math.h>

#define NB   8192
#define FST  257

__device__ unsigned g_m1[NB * 8];
__device__ unsigned g_m2[NB * 8];
__device__ float    g_f[NB * 64];
__device__ float    g_G[256 * 256];   // W1 @ W1^T
__device__ float    g_W3T[256 * 64];  // W3 transposed: [i][o]

typedef unsigned long long ull;
static __device__ __forceinline__ ull dup2(float x) {
    unsigned xi = __float_as_uint(x); ull r;
    asm("mov.b64 %0, {%1, %1};" : "=l"(r) : "r"(xi)); return r;
}
static __device__ __forceinline__ ull fma2(ull a, ull b, ull c) {
    ull d; asm("fma.rn.f32x2 %0, %1, %2, %3;" : "=l"(d) : "l"(a), "l"(b), "l"(c)); return d;
}
static __device__ __forceinline__ float2 unp2(ull v) {
    unsigned lo, hi; asm("mov.b64 {%0, %1}, %2;" : "=r"(lo), "=r"(hi) : "l"(v));
    return make_float2(__uint_as_float(lo), __uint_as_float(hi));
}

// ================= precompute: G = W1 W1^T, and W3T =================
__global__ void __launch_bounds__(256)
gram_kernel(const float* __restrict__ W1, const float* __restrict__ W3)
{
    __shared__ float At[64][65];
    __shared__ float Bt2[64][65];
    const int t = blockIdx.x;
    const int bi = t >> 2, bj = t & 3;
    const int tid = threadIdx.x;
    const int tx = tid & 15, ty = tid >> 4;

    // W3T fill (grid-strided, independent of G tiles)
    for (int e = t * 256 + tid; e < 256 * 64; e += 16 * 256) {
        int i = e >> 6, o = e & 63;
        g_W3T[e] = W3[(size_t)o * 256 + i];
    }

    float acc[4][4];
    #pragma unroll
    for (int i = 0; i < 4; i++)
        #pragma unroll
        for (int u = 0; u < 4; u++) acc[i][u] = 0.f;

    for (int kc = 0; kc < 4; kc++) {
        __syncthreads();
        for (int e = tid; e < 64 * 16; e += 256) {
            int r = e >> 4, c4 = e & 15;
            float4 va = reinterpret_cast<const float4*>(W1)[(size_t)(bi * 64 + r) * 64 + kc * 16 + c4];
            At[r][c4 * 4 + 0] = va.x; At[r][c4 * 4 + 1] = va.y;
            At[r][c4 * 4 + 2] = va.z; At[r][c4 * 4 + 3] = va.w;
            float4 vb = reinterpret_cast<const float4*>(W1)[(size_t)(bj * 64 + r) * 64 + kc * 16 + c4];
            Bt2[r][c4 * 4 + 0] = vb.x; Bt2[r][c4 * 4 + 1] = vb.y;
            Bt2[r][c4 * 4 + 2] = vb.z; Bt2[r][c4 * 4 + 3] = vb.w;
        }
        __syncthreads();
        #pragma unroll 4
        for (int k = 0; k < 64; k++) {
            float a[4], b[4];
            #pragma unroll
            for (int i = 0; i < 4; i++) a[i] = At[ty * 4 + i][k];
            #pragma unroll
            for (int u = 0; u < 4; u++) b[u] = Bt2[tx * 4 + u][k];
            #pragma unroll
            for (int i = 0; i < 4; i++)
                #pragma unroll
                for (int u = 0; u < 4; u++)
                    acc[i][u] = fmaf(a[i], b[u], acc[i][u]);
        }
    }
    #pragma unroll
    for (int i = 0; i < 4; i++)
        #pragma unroll
        for (int u = 0; u < 4; u++)
            g_G[(size_t)(bi * 64 + ty * 4 + i) * 256 + bj * 64 + tx * 4 + u] = acc[i][u];
}

// ================= forward: 3-layer MLP + masks (unchanged) =================
__global__ void __launch_bounds__(256, 1)
fwd_kernel(const float* __restrict__ x,
           const float* __restrict__ W1, const float* __restrict__ b1,
           const float* __restrict__ W2, const float* __restrict__ b2,
           const float* __restrict__ W3, const float* __restrict__ b3)
{
    extern __shared__ float sm[];
    float* bufA = sm;
    float* bufB = bufA + 64 * FST;
    float* wt   = bufB + 64 * FST;
    const int tid = threadIdx.x;
    const int s0  = blockIdx.x * 64;
    const int tx = tid & 15, ty = tid >> 4;

    for (int e = tid; e < 64 * 64; e += 256) {
        int r = e >> 6, c = e & 63;
        float4 v = reinterpret_cast<const float4*>(x)[(size_t)(s0 + r) * 64 + c];
        float* d = &bufA[r * FST + c * 4];
        d[0] = v.x; d[1] = v.y; d[2] = v.z; d[3] = v.w;
    }
    __syncthreads();

    const float* Ws[3] = {W1, W2, W3};
    const float* bs[3] = {b1, b2, b3};
    float* ib = bufA;
    float* ob = bufB;

    for (int L = 0; L < 3; L++) {
        const int HO = (L == 2) ? 64 : 256;
        for (int oc = 0; oc < HO / 64; oc++) {
            __syncthreads();
            for (int e = tid; e < 64 * 64; e += 256) {
                int r = e >> 6, c = e & 63;
                float4 v = reinterpret_cast<const float4*>(Ws[L])[(size_t)(oc * 64 + r) * 64 + c];
                float* d = &wt[r * FST + c * 4];
                d[0] = v.x; d[1] = v.y; d[2] = v.z; d[3] = v.w;
            }
            __syncthreads();

            float acc[4][4];
            #pragma unroll
            for (int u = 0; u < 4; u++) {
                float bv = bs[L][oc * 64 + tx + 16 * u];
                #pragma unroll
                for (int i = 0; i < 4; i++) acc[i][u] = bv;
            }
            #pragma unroll 4
            for (int k = 0; k < 256; k++) {
                float a[4], bv[4];
                #pragma unroll
                for (int i = 0; i < 4; i++) a[i] = ib[(ty * 4 + i) * FST + k];
                #pragma unroll
                for (int u = 0; u < 4; u++) bv[u] = wt[(tx + 16 * u) * FST + k];
                #pragma unroll
                for (int i = 0; i < 4; i++)
                    #pragma unroll
                    for (int u = 0; u < 4; u++)
                        acc[i][u] = fmaf(a[i], bv[u], acc[i][u]);
            }
            if (L < 2) {
                #pragma unroll
                for (int i = 0; i < 4; i++)
                    #pragma unroll
                    for (int u = 0; u < 4; u++)
                        ob[(ty * 4 + i) * FST + oc * 64 + tx + 16 * u] = fmaxf(acc[i][u], 0.f);
            } else {
                #pragma unroll
                for (int i = 0; i < 4; i++)
                    #pragma unroll
                    for (int u = 0; u < 4; u++)
                        g_f[(size_t)(s0 + ty * 4 + i) * 64 + tx + 16 * u] = acc[i][u];
            }
        }
        if (L < 2) {
            __syncthreads();
            unsigned* mg = L ? g_m2 : g_m1;
            for (int e = tid; e < 64 * 8; e += 256) {
                int s = e >> 3, w = e & 7;
                unsigned bits = 0;
                for (int bb = 0; bb < 32; bb++)
                    if (ob[s * FST + w * 32 + bb] > 0.f) bits |= 1u << bb;
                mg[(size_t)(s0 + s) * 8 + w] = bits;
            }
            float* t = ib; ib = ob; ob = t;
            __syncthreads();
        }
    }
}

// ================= Jacobian Frobenius norm v2 =================
// q = sum_{j,j' in S1} (Bt^T Bt)[j,j'] * G[idx1[j], idx1[j']],
// Bt[o,j] = sum_{i in S2} W3T[i][o] * W2[i, idx1[j]]
#define BT_ST  200
#define WS2_ST 257
#define AS_ST  72
#define WG_ST  196
#define O_BT   0
#define O_WS2  (64 * BT_ST)
#define O_AS   (O_WS2 + 16 * WS2_ST)
#define O_WG   (O_AS + 16 * AS_ST)
#define O_IDX1 (O_WG + 16 * WG_ST)
#define O_IDX2 (O_IDX1 + 256)
#define O_CNT  (O_IDX2 + 256)
#define O_PC   (O_CNT + 2)
#define O_RED  (O_PC + 16)
#define SMEMF  (O_RED + 10)
#define SMEMB  (SMEMF * 4)

__global__ void __launch_bounds__(256, 2)
jac_kernel(const float* __restrict__ W2, const float* __restrict__ kp,
           float* __restrict__ out)
{
    extern __shared__ float sm[];
    float* Bt  = sm + O_BT;
    float* Ws2 = sm + O_WS2;
    float* As  = sm + O_AS;
    float* Wg  = sm + O_WG;
    int* idx1  = (int*)(sm + O_IDX1);
    int* idx2  = (int*)(sm + O_IDX2);
    int* cnts  = (int*)(sm + O_CNT);
    int* pcnt  = (int*)(sm + O_PC);
    float* red = sm + O_RED;

    const int b = blockIdx.x;
    const int tid = threadIdx.x;

    // ---- compaction ----
    idx1[tid] = 0; idx2[tid] = 0;
    if (tid < 16) {
        int which = tid >> 3, w = tid & 7;
        unsigned word = (which ? g_m2 : g_m1)[(size_t)b * 8 + w];
        pcnt[tid] = __popc(word);
    }
    __syncthreads();
    if (tid < 16) {
        int which = tid >> 3, w = tid & 7;
        unsigned word = (which ? g_m2 : g_m1)[(size_t)b * 8 + w];
        int base = 0;
        for (int t = which * 8; t < which * 8 + w; t++) base += pcnt[t];
        int* idx = which ? idx2 : idx1;
        while (word) {
            int bp = __ffs(word) - 1; word &= word - 1;
            idx[base++] = w * 32 + bp;
        }
        if (w == 7) cnts[which] = base;
    }
    __syncthreads();
    const int cnt1 = min(cnts[0], 192);
    const int cnt2 = cnts[1];
    int n1r = (cnt1 + 63) & ~63;
    if (n1r == 0) n1r = 64;
    const int n1b = n1r >> 6;
    const int nch = (cnt2 + 15) >> 4;

    // ---- phase 1: Bt[64][n1r], register accumulators ----
    const int o0 = (tid & 7) * 8;
    const int j0 = (tid >> 3) * 8;
    const bool act = (j0 < n1r);

    ull acc[8][4];
    #pragma unroll
    for (int k = 0; k < 8; k++)
        #pragma unroll
        for (int c = 0; c < 4; c++) acc[k][c] = 0ull;

    for (int ch = 0; ch < nch; ch++) {
        const int i0 = ch * 16;
        __syncthreads();
        for (int e = tid; e < 16 * 64; e += 256) {
            int ii = e >> 6, c4 = e & 63;
            int row = idx2[i0 + ii];
            float4 v = reinterpret_cast<const float4*>(W2)[(size_t)row * 64 + c4];
            float* d = &Ws2[ii * WS2_ST + c4 * 4];
            d[0] = v.x; d[1] = v.y; d[2] = v.z; d[3] = v.w;
        }
        for (int e = tid; e < 16 * 16; e += 256) {
            int ii = e >> 4, c4 = e & 15;
            float4 v = make_float4(0.f, 0.f, 0.f, 0.f);
            if (i0 + ii < cnt2)
                v = reinterpret_cast<const float4*>(g_W3T)[(size_t)idx2[i0 + ii] * 16 + c4];
            float* d = &As[ii * AS_ST + c4 * 4];
            d[0] = v.x; d[1] = v.y; d[2] = v.z; d[3] = v.w;
        }
        __syncthreads();
        for (int e = tid; e < 16 * 192; e += 256) {
            int ii = e / 192, j = e - ii * 192;
            Wg[ii * WG_ST + j] = (j < cnt1) ? Ws2[ii * WS2_ST + idx1[j]] : 0.f;
        }
        __syncthreads();
        if (act) {
            #pragma unroll 4
            for (int ii = 0; ii < 16; ii++) {
                float a[8]; ull wv[4];
                #pragma unroll
                for (int k = 0; k < 8; k++) a[k] = As[ii * AS_ST + o0 + k];
                #pragma unroll
                for (int c = 0; c < 4; c++) wv[c] = *(const ull*)&Wg[ii * WG_ST + j0 + 2 * c];
                #pragma unroll
                for (int k = 0; k < 8; k++) {
                    ull ad = dup2(a[k]);
                    #pragma unroll
                    for (int c = 0; c < 4; c++) acc[k][c] = fma2(ad, wv[c], acc[k][c]);
                }
            }
        }
    }
    __syncthreads();
    if (act) {
        #pragma unroll
        for (int k = 0; k < 8; k++)
            #pragma unroll
            for (int c = 0; c < 4; c++)
                *(ull*)&Bt[(o0 + k) * BT_ST + j0 + 2 * c] = acc[k][c];
    }
    __syncthreads();

    // ---- phase 2: q = sum M[j,j'] * G[idx1[j], idx1[j']] ----
    int pa[6], pb[6], np = 0;
    for (int a2 = 0; a2 < n1b; a2++)
        for (int b2 = a2; b2 < n1b; b2++) { pa[np] = a2; pb[np] = b2; np++; }

    const int grp = tid >> 6, tt = tid & 63;
    const int r8 = (tt >> 3) * 8, c8 = (tt & 7) * 8;
    float qacc = 0.f;

    for (int p = grp; p < np; p += 4) {
        const int ja = pa[p] * 64, jb = pb[p] * 64;
        const float w = (pa[p] == pb[p]) ? 1.f : 2.f;
        #pragma unroll
        for (int k = 0; k < 8; k++)
            #pragma unroll
            for (int c = 0; c < 4; c++) acc[k][c] = 0ull;
        #pragma unroll 2
        for (int o = 0; o < 64; o++) {
            float ba[8]; ull bb[4];
            #pragma unroll
            for (int k = 0; k < 8; k++) ba[k] = Bt[o * BT_ST + ja + r8 + k];
            #pragma unroll
            for (int c = 0; c < 4; c++) bb[c] = *(const ull*)&Bt[o * BT_ST + jb + c8 + 2 * c];
            #pragma unroll
            for (int k = 0; k < 8; k++) {
                ull ad = dup2(ba[k]);
                #pragma unroll
                for (int c = 0; c < 4; c++) acc[k][c] = fma2(ad, bb[c], acc[k][c]);
            }
        }
        float part = 0.f;
        #pragma unroll
        for (int k = 0; k < 8; k++) {
            const float* Grow = &g_G[(size_t)idx1[ja + r8 + k] * 256];
            #pragma unroll
            for (int c = 0; c < 4; c++) {
                float2 m = unp2(acc[k][c]);
                part += m.x * Grow[idx1[jb + c8 + 2 * c]];
                part += m.y * Grow[idx1[jb + c8 + 2 * c + 1]];
            }
        }
        qacc += w * part;
    }

    // ---- reduce + epilogue ----
    #pragma unroll
    for (int s = 16; s; s >>= 1) qacc += __shfl_xor_sync(0xFFFFFFFFu, qacc, s);
    if ((tid & 31) == 0) red[tid >> 5] = qacc;
    __syncthreads();
    if (tid == 0) {
        float t = 0.f;
        for (int i = 0; i < 8; i++) t += red[i];
        red[0] = t;
    }
    __syncthreads();
    const float qq = red[0];
    if (tid < 64) {
        float fv = g_f[(size_t)b * 64 + tid];
        float kk = kp[0];
        float sp = (kk > 20.f) ? kk : log1pf(expf(kk));
        out[(size_t)b * 64 + tid] = tanhf(sp * fv / (sqrtf(qq) + 1e-4f));
    }
}

extern "C" void kernel_launch(void* const* d_in, const int* in_sizes, int n_in,
                              void* d_out, int out_size) {
    const float* x  = (const float*)d_in[0];
    const float* W1 = (const float*)d_in[1];
    const float* b1 = (const float*)d_in[2];
    const float* W2 = (const float*)d_in[3];
    const float* b2 = (const float*)d_in[4];
    const float* W3 = (const float*)d_in[5];
    const float* b3 = (const float*)d_in[6];
    const float* k  = (const float*)d_in[7];
    float* out = (float*)d_out;

    const size_t sm_fwd = 3 * 64 * FST * sizeof(float);
    cudaFuncSetAttribute(fwd_kernel, cudaFuncAttributeMaxDynamicSharedMemorySize, (int)sm_fwd);
    cudaFuncSetAttribute(jac_kernel, cudaFuncAttributeMaxDynamicSharedMemorySize, SMEMB);

    gram_kernel<<<16, 256>>>(W1, W3);
    fwd_kernel<<<128, 256, sm_fwd>>>(x, W1, b1, W2, b2, W3, b3);
    jac_kernel<<<NB, 256, SMEMB>>>(W2, k, out);
}